// round 10
// baseline (speedup 1.0000x reference)
#include <cuda_runtime.h>
#include <stdint.h>

// Problem constants (fixed shapes)
#define NN   10000       // nodes
#define BB   4           // batch
#define FIN  16          // input features
#define TT   8           // time steps
#define CCH  32          // cheb channels
#define CTM  64          // time channels
#define MAXE 160000      // edges
#define ITERS 64         // power iterations
#define CSZ  8           // cluster size (CTAs) for k_power
#define NPC  1250        // nodes per CTA (NN / CSZ)
#define TOTX (NN*512)    // Tx element count = N * F(16) * TB(32)

// ---------------- scratch (device globals; no allocation) ----------------
__device__ __align__(16) float g_Tx0[TOTX];
__device__ __align__(16) float g_Tx1[TOTX];
__device__ __align__(16) float g_cheb[NN*1024];   // [n][tb(32)][c(32)]
__device__ int   g_indeg[NN];
__device__ int   g_rowptr[NN+1];
__device__ int   g_cursor[NN];
__device__ int   g_col[MAXE];
__device__ float g_S[ITERS+1];
__device__ float g_lmax;
__device__ float g_diag[NN];

// ---------------- packed f32x2 helpers (sm_100a) -------------------------
__device__ __forceinline__ unsigned long long pk2(float a, float b) {
    unsigned long long r;
    asm("mov.b64 %0, {%1, %2};" : "=l"(r) : "f"(a), "f"(b));
    return r;
}
__device__ __forceinline__ void fma2(unsigned long long& d, unsigned long long a, unsigned long long b) {
    asm("fma.rn.f32x2 %0, %1, %2, %0;" : "+l"(d) : "l"(a), "l"(b));
}
__device__ __forceinline__ float2 upk2(unsigned long long v) {
    float2 f;
    asm("mov.b64 {%0, %1}, %2;" : "=f"(f.x), "=f"(f.y) : "l"(v));
    return f;
}

__device__ __forceinline__ uint32_t smem_u32(const void* p) {
    uint32_t a;
    asm("{ .reg .u64 t; cvta.to.shared.u64 t, %1; cvt.u32.u64 %0, t; }" : "=r"(a) : "l"(p));
    return a;
}

// Push value v to smem address `addr` in ALL cluster CTAs (incl. self).
__device__ __forceinline__ void push_all(uint32_t addr, float v) {
#pragma unroll
    for (int p = 0; p < CSZ; p++) {
        uint32_t ra;
        asm("mapa.shared::cluster.u32 %0, %1, %2;" : "=r"(ra) : "r"(addr), "r"(p));
        asm volatile("st.shared::cluster.f32 [%0], %1;" :: "r"(ra), "f"(v) : "memory");
    }
}

// ---------------- CSR build --------------------------------------------
__global__ void k_zero() {
    int i = blockIdx.x * blockDim.x + threadIdx.x;
    if (i < NN) g_indeg[i] = 0;
    if (i <= ITERS) g_S[i] = 0.0f;
}

__global__ void k_hist(const int* __restrict__ dst, int E) {
    int e = blockIdx.x * blockDim.x + threadIdx.x;
    if (e < E) atomicAdd(&g_indeg[dst[e]], 1);
}

__global__ void k_scan() {   // 1 block, 1024 threads
    __shared__ int ps[1024];
    const int CH = 10;       // 1024*10 >= NN
    int t = threadIdx.x;
    int base = t * CH;
    int sum = 0;
#pragma unroll
    for (int i = 0; i < CH; i++) { int idx = base + i; if (idx < NN) sum += g_indeg[idx]; }
    ps[t] = sum; __syncthreads();
    for (int off = 1; off < 1024; off <<= 1) {
        int v = ps[t];
        int a = (t >= off) ? ps[t - off] : 0;
        __syncthreads();
        ps[t] = v + a;
        __syncthreads();
    }
    int run = (t == 0) ? 0 : ps[t - 1];
#pragma unroll
    for (int i = 0; i < CH; i++) {
        int idx = base + i;
        if (idx < NN) { g_rowptr[idx] = run; g_cursor[idx] = run; run += g_indeg[idx]; }
    }
    if (t == 1023) g_rowptr[NN] = ps[1023];
}

__global__ void k_fill(const int* __restrict__ src, const int* __restrict__ dst, int E) {
    int e = blockIdx.x * blockDim.x + threadIdx.x;
    if (e < E) {
        int p = atomicAdd(&g_cursor[dst[e]], 1);
        g_col[p] = src[e];
    }
}

// ---------------- power iteration: single 8-CTA cluster, HW barriers -----
// The 40KB iterate is replicated in each CTA's smem, double-buffered.
// Per iteration: compute own 1250 nodes from local copy (LDS gathers),
// push new values to all CTAs' next buffer via DSMEM, smem-tree norm
// reduce, atomicAdd partial to g_S[k], threadfence, cluster.sync.
// Per-node arithmetic identical to prior passing rounds:
//   iter 1: w = fl(deg*C0) - chain_deg(C0)   (null-space rounding residue)
//   iter k: acc = (deg*cur[n] - sum cur[col]) * (1/sqrt(S[k-1]))
__global__ void __cluster_dims__(CSZ, 1, 1) __launch_bounds__(1024, 1)
k_power() {
    extern __shared__ __align__(16) float dyn[];   // [2][NN] double buffer
    __shared__ float red[1024];
    uint32_t rank;
    asm("mov.u32 %0, %%cluster_ctarank;" : "=r"(rank));
    int tid = threadIdx.x;
    const float C0 = 0.01f;                 // 1/sqrt(10000) rounded to f32

    int base = (int)rank * NPC;
    int n0 = base + tid;                    // always valid (tid < 1024 < 1250)
    int n1 = base + 1024 + tid;
    bool v1 = (tid < NPC - 1024);           // tid < 226
    int e00 = g_rowptr[n0];
    int m0  = g_rowptr[n0 + 1] - e00;
    int e01 = 0, m1 = 0;
    if (v1) { e01 = g_rowptr[n1]; m1 = g_rowptr[n1 + 1] - e01; }
    float deg0 = (float)m0, deg1 = (float)m1;

    uint32_t buf_addr = smem_u32(dyn);

    for (int k = 1; k <= ITERS; k++) {
        float part = 0.0f;
        uint32_t nxt = buf_addr + (uint32_t)(k & 1) * (NN * 4);
        const float* cur = dyn + ((k - 1) & 1) * NN;
        if (k == 1) {
            {
                float av = 0.0f;
                for (int j = 0; j < m0; j++) av = __fadd_rn(av, C0);
                float w = __fsub_rn(__fmul_rn(deg0, C0), av);
                push_all(nxt + (uint32_t)n0 * 4, w);
                part += w * w;
            }
            if (v1) {
                float av = 0.0f;
                for (int j = 0; j < m1; j++) av = __fadd_rn(av, C0);
                float w = __fsub_rn(__fmul_rn(deg1, C0), av);
                push_all(nxt + (uint32_t)n1 * 4, w);
                part += w * w;
            }
        } else {
            float inv = 1.0f / sqrtf(__ldcg(&g_S[k - 1]));
            {
                float acc = deg0 * cur[n0];
#pragma unroll 4
                for (int j = 0; j < m0; j++) acc -= cur[g_col[e00 + j]];
                acc *= inv;
                push_all(nxt + (uint32_t)n0 * 4, acc);
                part += acc * acc;
            }
            if (v1) {
                float acc = deg1 * cur[n1];
#pragma unroll 4
                for (int j = 0; j < m1; j++) acc -= cur[g_col[e01 + j]];
                acc *= inv;
                push_all(nxt + (uint32_t)n1 * 4, acc);
                part += acc * acc;
            }
        }
        red[tid] = part; __syncthreads();
        for (int s = 512; s > 0; s >>= 1) {
            if (tid < s) red[tid] += red[tid + s];
            __syncthreads();
        }
        if (tid == 0) {
            atomicAdd(&g_S[k], red[0]);
            __threadfence();
        }
        asm volatile("barrier.cluster.arrive.aligned;" ::: "memory");
        asm volatile("barrier.cluster.wait.aligned;" ::: "memory");
    }
    float lm = sqrtf(__ldcg(&g_S[ITERS]));
    if (rank == 0 && tid == 0) g_lmax = lm;
    for (int i = (int)rank * 1024 + tid; i < NN; i += CSZ * 1024)
        g_diag[i] = 2.0f * (float)g_indeg[i] / lm - 1.0f;
}

// ---------------- permute X(B,N,F,T) -> Tx0 = (F,B,N,T) flat -------------
// The reference's reshape makes graph row n2 = flat[(n2*512):(n2*512+512)]
// of the (F,B,N,T) array, so this simple transpose IS the required layout
// (inner row layout: [f2(16)][tb(32)]).
__global__ void k_permute(const float* __restrict__ X) {
    int i = blockIdx.x * blockDim.x + threadIdx.x;   // [0, 640000)
    if (i >= NN * BB * FIN) return;
    int f = i / (BB * NN);
    int r = i - f * (BB * NN);
    int b = r / NN;
    int n = r - b * NN;
    const float4* src = reinterpret_cast<const float4*>(X + ((size_t)((b * NN + n) * FIN + f)) * TT);
    float4* dst = reinterpret_cast<float4*>(g_Tx0 + (size_t)i * TT);
    dst[0] = src[0];
    dst[1] = src[1];
}

// ---------------- lhat1: Tx1 = diag*Tx0 - off * A^T Tx0 -----------------
__global__ void k_lhat1() {
    int n = blockIdx.x;
    int t = threadIdx.x;   // 0..127, float4 chunk of the 512-float row
    const float4* x0 = reinterpret_cast<const float4*>(g_Tx0);
    float4 acc = make_float4(0.f, 0.f, 0.f, 0.f);
    int e0 = g_rowptr[n], e1 = g_rowptr[n + 1];
    for (int j = e0; j < e1; j++) {
        int s = g_col[j];
        float4 v = x0[s * 128 + t];
        acc.x += v.x; acc.y += v.y; acc.z += v.z; acc.w += v.w;
    }
    float off = 2.0f / g_lmax;
    float dg  = g_diag[n];
    float4 xx = x0[n * 128 + t];
    float4 o;
    o.x = dg * xx.x - off * acc.x;
    o.y = dg * xx.y - off * acc.y;
    o.z = dg * xx.z - off * acc.z;
    o.w = dg * xx.w - off * acc.w;
    reinterpret_cast<float4*>(g_Tx1)[n * 128 + t] = o;
}

// ------- lhat2 (Tx2 = 2*lhat(Tx1)-Tx0) fused with Cheb GEMM + ReLU ------
// Rows f-major: element (f2, tb) at local index f2*32 + tb.
__global__ void k_lhat2cheb(const float* __restrict__ chebW, const float* __restrict__ chebB) {
    __shared__ __align__(16) float sT[1536];   // Tx0,Tx1,Tx2 rows of this node
    __shared__ float sW[1536];                 // cheb_W (3,16,32)
    __shared__ float sB[CCH];
    int n = blockIdx.x;
    int t = threadIdx.x;   // 128 threads
    for (int i = t; i < 1536; i += 128) sW[i] = chebW[i];
    if (t < CCH) sB[t] = chebB[t];

    const float4* x0 = reinterpret_cast<const float4*>(g_Tx0);
    const float4* x1 = reinterpret_cast<const float4*>(g_Tx1);
    float4 acc = make_float4(0.f, 0.f, 0.f, 0.f);
    int e0 = g_rowptr[n], e1 = g_rowptr[n + 1];
    for (int j = e0; j < e1; j++) {
        int s = g_col[j];
        float4 v = x1[s * 128 + t];
        acc.x += v.x; acc.y += v.y; acc.z += v.z; acc.w += v.w;
    }
    float off = 2.0f / g_lmax;
    float dg  = g_diag[n];
    float4 a1 = x1[n * 128 + t];
    float4 a0 = x0[n * 128 + t];
    float4 t2;
    t2.x = 2.f * (dg * a1.x - off * acc.x) - a0.x;
    t2.y = 2.f * (dg * a1.y - off * acc.y) - a0.y;
    t2.z = 2.f * (dg * a1.z - off * acc.z) - a0.z;
    t2.w = 2.f * (dg * a1.w - off * acc.w) - a0.w;
    reinterpret_cast<float4*>(sT)[t]       = a0;   // Tx0 row (f-major)
    reinterpret_cast<float4*>(sT)[128 + t] = a1;   // Tx1 row
    reinterpret_cast<float4*>(sT)[256 + t] = t2;   // Tx2 row
    __syncthreads();

    // out[tb][c] = relu(b_c + sum_k sum_f Txk[f][tb]*W[k][f][c])
    int tb = t >> 2;
    int c0 = (t & 3) << 3;   // 8 channels per thread
    float y[8];
#pragma unroll
    for (int i = 0; i < 8; i++) y[i] = 0.f;
#pragma unroll
    for (int k = 0; k < 3; k++) {
        const float* xr = sT + k * 512 + tb;       // element f at xr[f*32]
        const float* wk = sW + k * 512;
#pragma unroll
        for (int f = 0; f < FIN; f++) {
            float xv = xr[f * 32];
            const float* wr = wk + f * 32 + c0;
#pragma unroll
            for (int i = 0; i < 8; i++) y[i] += xv * wr[i];
        }
    }
    float* outp = g_cheb + n * 1024 + tb * 32 + c0;
#pragma unroll
    for (int i = 0; i < 8; i++) outp[i] = fmaxf(y[i] + sB[c0 + i], 0.f);
}

// ------- final: time conv + residual + ReLU + LayerNorm + write ---------
// per (b,n) unit: Y(64x8) = A(64x112) * Z(112x8) + bias ; relu ; LN over 64
// GEMM uses packed fma.rn.f32x2 (identical rounding to scalar FFMA chain).
__global__ void k_final(const float* __restrict__ X,
                        const float* __restrict__ timeW, const float* __restrict__ timeB,
                        const float* __restrict__ resW,  const float* __restrict__ resB,
                        const float* __restrict__ gamma, const float* __restrict__ beta,
                        float* __restrict__ out) {
    __shared__ float As[112 * 64];                   // transposed: As[kk*64+co]
    __shared__ __align__(16) float Zs[4][896];       // per-group Z (112x8)
    __shared__ float sBias[64], sG[64], sBt[64];
    __shared__ float redS[4][2][8], redQ[4][2][8];
    int tid = threadIdx.x;

    for (int i = tid; i < 7168; i += 256) {
        int kk = i >> 6, co = i & 63;
        float w;
        if (kk < 96) { int ci = kk / 3, dt = kk - ci * 3; w = timeW[co * 96 + ci * 3 + dt]; }
        else         { w = resW[co * 16 + (kk - 96)]; }
        As[i] = w;
    }
    if (tid < 64) { sBias[tid] = timeB[tid] + resB[tid]; sG[tid] = gamma[tid]; sBt[tid] = beta[tid]; }
    __syncthreads();

    int g = tid >> 6, co = tid & 63;
    int lane = tid & 31, wsub = (tid >> 5) & 1;

    for (int round = 0; round < 8; round++) {
        int unit = blockIdx.x * 32 + round * 4 + g;   // 0..39999
        int b = unit / NN, n = unit - b * NN;

        // build Z: kk<96 -> time-conv patch (ci,dt), kk>=96 -> residual X
        const float* cbase = g_cheb + n * 1024 + b * 256;       // [tau*32+ci]
        const float* xbase = X + (size_t)(b * NN + n) * 128;    // [f*8+t]
        float* Z = Zs[g];
        for (int i = co; i < 896; i += 64) {
            int kk = i >> 3, t = i & 7;
            float v;
            if (kk < 96) {
                int ci = kk / 3, dt = kk - ci * 3;
                int tau = t + dt - 1;
                v = (tau >= 0 && tau < TT) ? cbase[tau * 32 + ci] : 0.f;
            } else {
                v = xbase[(kk - 96) * 8 + t];
            }
            Z[i] = v;
        }
        __syncthreads();

        float bco = sBias[co];
        unsigned long long y01 = pk2(bco, bco);
        unsigned long long y23 = pk2(bco, bco);
        unsigned long long y45 = pk2(bco, bco);
        unsigned long long y67 = pk2(bco, bco);
        const float4* Z4 = reinterpret_cast<const float4*>(Z);
        const float*  Ap = As + co;
#pragma unroll 4
        for (int kk = 0; kk < 112; kk++) {
            float a = Ap[kk * 64];
            unsigned long long aa = pk2(a, a);
            float4 z0 = Z4[kk * 2];
            float4 z1 = Z4[kk * 2 + 1];
            fma2(y01, aa, pk2(z0.x, z0.y));
            fma2(y23, aa, pk2(z0.z, z0.w));
            fma2(y45, aa, pk2(z1.x, z1.y));
            fma2(y67, aa, pk2(z1.z, z1.w));
        }
        float y[8];
        { float2 p = upk2(y01); y[0] = p.x; y[1] = p.y; }
        { float2 p = upk2(y23); y[2] = p.x; y[3] = p.y; }
        { float2 p = upk2(y45); y[4] = p.x; y[5] = p.y; }
        { float2 p = upk2(y67); y[6] = p.x; y[7] = p.y; }
#pragma unroll
        for (int t = 0; t < 8; t++) y[t] = fmaxf(y[t], 0.f);

        // LayerNorm over 64 channels — two-pass (matches jnp.var semantics)
        float s[8];
#pragma unroll
        for (int t = 0; t < 8; t++) s[t] = y[t];
#pragma unroll
        for (int off = 16; off > 0; off >>= 1) {
#pragma unroll
            for (int t = 0; t < 8; t++) s[t] += __shfl_xor_sync(0xffffffffu, s[t], off);
        }
        if (lane == 0) {
#pragma unroll
            for (int t = 0; t < 8; t++) redS[g][wsub][t] = s[t];
        }
        __syncthreads();

        float mu[8], q[8];
#pragma unroll
        for (int t = 0; t < 8; t++) {
            mu[t] = (redS[g][0][t] + redS[g][1][t]) * (1.f / 64.f);
            float d = y[t] - mu[t];
            q[t] = d * d;
        }
#pragma unroll
        for (int off = 16; off > 0; off >>= 1) {
#pragma unroll
            for (int t = 0; t < 8; t++) q[t] += __shfl_xor_sync(0xffffffffu, q[t], off);
        }
        if (lane == 0) {
#pragma unroll
            for (int t = 0; t < 8; t++) redQ[g][wsub][t] = q[t];
        }
        __syncthreads();

        float ov[8];
#pragma unroll
        for (int t = 0; t < 8; t++) {
            float var = (redQ[g][0][t] + redQ[g][1][t]) * (1.f / 64.f);
            float inv = rsqrtf(var + 1e-5f);
            ov[t] = (y[t] - mu[t]) * inv * sG[co] + sBt[co];
        }
        float4* op = reinterpret_cast<float4*>(out + ((size_t)unit * 64 + co) * 8);
        op[0] = make_float4(ov[0], ov[1], ov[2], ov[3]);
        op[1] = make_float4(ov[4], ov[5], ov[6], ov[7]);
    }
}

// ---------------- launch ----------------
extern "C" void kernel_launch(void* const* d_in, const int* in_sizes, int n_in,
                              void* d_out, int out_size) {
    const float* X     = (const float*)d_in[0];
    const int*   ei    = (const int*)  d_in[1];
    const float* chebW = (const float*)d_in[2];
    const float* chebB = (const float*)d_in[3];
    const float* timeW = (const float*)d_in[4];
    const float* timeB = (const float*)d_in[5];
    const float* resW  = (const float*)d_in[6];
    const float* resB  = (const float*)d_in[7];
    const float* gam   = (const float*)d_in[8];
    const float* bet   = (const float*)d_in[9];
    float* out = (float*)d_out;

    int E = in_sizes[1] / 2;
    const int* src = ei;
    const int* dst = ei + E;
    int EB = (E + 255) / 256;

    static int smem_set = 0;
    if (!smem_set) {
        cudaFuncSetAttribute(k_power, cudaFuncAttributeMaxDynamicSharedMemorySize,
                             2 * NN * (int)sizeof(float));
        smem_set = 1;
    }

    k_zero<<<(NN + 255) / 256, 256>>>();
    k_hist<<<EB, 256>>>(dst, E);
    k_scan<<<1, 1024>>>();
    k_fill<<<EB, 256>>>(src, dst, E);
    k_power<<<CSZ, 1024, 2 * NN * sizeof(float)>>>();
    k_permute<<<(NN * BB * FIN + 255) / 256, 256>>>(X);
    k_lhat1<<<NN, 128>>>();
    k_lhat2cheb<<<NN, 128>>>(chebW, chebB);
    k_final<<<1250, 256>>>(X, timeW, timeB, resW, resB, gam, bet, out);
}

// round 12
// speedup vs baseline: 1.1569x; 1.1569x over previous
#include <cuda_runtime.h>
#include <stdint.h>

// Resubmission of round-11 kernel: bench died with an async-runner
// ExceptionGroup (no compile error, no rel_err, no harness rc) — treated
// as infrastructure flake. Code byte-identical in all functional respects.

// Problem constants (fixed shapes)
#define NN   10000       // nodes
#define BB   4           // batch
#define FIN  16          // input features
#define TT   8           // time steps
#define CCH  32          // cheb channels
#define CTM  64          // time channels
#define MAXE 160000      // edges
#define ITERS 64         // power iterations
#define CSZ  8           // cluster size (CTAs) for k_power
#define NPC  1250        // nodes per CTA (NN / CSZ)
#define ECAP 24000       // per-CTA smem edge cache capacity (mean 20000)
#define TOTX (NN*512)    // Tx element count = N * F(16) * TB(32)

// ---------------- scratch (device globals; no allocation) ----------------
__device__ __align__(16) float g_Tx0[TOTX];
__device__ __align__(16) float g_Tx1[TOTX];
__device__ __align__(16) float g_cheb[NN*1024];   // [n][tb(32)][c(32)]
__device__ int   g_indeg[NN];
__device__ int   g_rowptr[NN+1];
__device__ int   g_cursor[NN];
__device__ int   g_col[MAXE];
__device__ __align__(16) float g_u0[NN];
__device__ __align__(16) float g_u1[NN];
__device__ float g_S[ITERS+1];
__device__ float g_lmax;
__device__ float g_diag[NN];

// ---------------- packed f32x2 helpers (sm_100a) -------------------------
__device__ __forceinline__ unsigned long long pk2(float a, float b) {
    unsigned long long r;
    asm("mov.b64 %0, {%1, %2};" : "=l"(r) : "f"(a), "f"(b));
    return r;
}
__device__ __forceinline__ void fma2(unsigned long long& d, unsigned long long a, unsigned long long b) {
    asm("fma.rn.f32x2 %0, %1, %2, %0;" : "+l"(d) : "l"(a), "l"(b));
}
__device__ __forceinline__ float2 upk2(unsigned long long v) {
    float2 f;
    asm("mov.b64 {%0, %1}, %2;" : "=f"(f.x), "=f"(f.y) : "l"(v));
    return f;
}

// ---------------- CSR build --------------------------------------------
__global__ void k_zero() {
    int i = blockIdx.x * blockDim.x + threadIdx.x;
    if (i < NN) g_indeg[i] = 0;
    if (i <= ITERS) g_S[i] = 0.0f;
}

__global__ void k_hist(const int* __restrict__ dst, int E) {
    int e = blockIdx.x * blockDim.x + threadIdx.x;
    if (e < E) atomicAdd(&g_indeg[dst[e]], 1);
}

__global__ void k_scan() {   // 1 block, 1024 threads
    __shared__ int ps[1024];
    const int CH = 10;       // 1024*10 >= NN
    int t = threadIdx.x;
    int base = t * CH;
    int sum = 0;
#pragma unroll
    for (int i = 0; i < CH; i++) { int idx = base + i; if (idx < NN) sum += g_indeg[idx]; }
    ps[t] = sum; __syncthreads();
    for (int off = 1; off < 1024; off <<= 1) {
        int v = ps[t];
        int a = (t >= off) ? ps[t - off] : 0;
        __syncthreads();
        ps[t] = v + a;
        __syncthreads();
    }
    int run = (t == 0) ? 0 : ps[t - 1];
#pragma unroll
    for (int i = 0; i < CH; i++) {
        int idx = base + i;
        if (idx < NN) { g_rowptr[idx] = run; g_cursor[idx] = run; run += g_indeg[idx]; }
    }
    if (t == 1023) g_rowptr[NN] = ps[1023];
}

__global__ void k_fill(const int* __restrict__ src, const int* __restrict__ dst, int E) {
    int e = blockIdx.x * blockDim.x + threadIdx.x;
    if (e < E) {
        int p = atomicAdd(&g_cursor[dst[e]], 1);
        g_col[p] = src[e];
    }
}

// ---------------- power iteration: 8-CTA cluster, HW barriers ------------
// Per-node arithmetic/order identical to prior passing rounds:
//   iter 1: w = fl(deg*C0) - chain_deg(C0)   (null-space rounding residue)
//   iter k: acc = (deg*cur[n] - sum cur[col]) * (1/sqrt(S[k-1]))
// Data movement: each CTA caches its CSR slice in smem once; per iteration
// it stages the full 40KB iterate from L2 into smem, computes its 1250
// nodes (pure LDS gathers), writes them coalesced to the global double
// buffer, reduces its norm partial (smem tree), atomicAdds to g_S[k],
// fences, and crosses one HW cluster barrier (~380cyc).
__global__ void __cluster_dims__(CSZ, 1, 1) __launch_bounds__(1024, 1)
k_power() {
    extern __shared__ __align__(16) float dyn[];   // [NN] vector + [ECAP] edges
    float* sm = dyn;
    int*   se = reinterpret_cast<int*>(dyn + NN);
    __shared__ float red[1024];
    uint32_t rank;
    asm("mov.u32 %0, %%cluster_ctarank;" : "=r"(rank));
    int tid = threadIdx.x;
    const float C0 = 0.01f;                 // 1/sqrt(10000) rounded to f32

    int base  = (int)rank * NPC;
    int ebase = g_rowptr[base];
    int ecnt  = g_rowptr[base + NPC] - ebase;
    bool fastE = (ecnt <= ECAP);
    // cache this CTA's edge slice (coalesced; once)
    for (int i = tid; i < ecnt && i < ECAP; i += 1024)
        se[i] = g_col[ebase + i];

    int n0 = base + tid;                    // always valid (tid < 1024 < 1250)
    int n1 = base + 1024 + tid;
    bool v1 = (tid < NPC - 1024);           // tid < 226
    int l00 = g_rowptr[n0] - ebase;
    int m0  = g_rowptr[n0 + 1] - (l00 + ebase);
    int l01 = 0, m1 = 0;
    if (v1) { l01 = g_rowptr[n1] - ebase; m1 = g_rowptr[n1 + 1] - (l01 + ebase); }
    float deg0 = (float)m0, deg1 = (float)m1;
    __syncthreads();

    float* cur = g_u0;   // read buffer for iter k (k>=2)
    float* nxt = g_u1;   // write buffer for iter k
    for (int k = 1; k <= ITERS; k++) {
        float part = 0.0f;
        if (k == 1) {
            {
                float av = 0.0f;
                for (int j = 0; j < m0; j++) av = __fadd_rn(av, C0);
                float w = __fsub_rn(__fmul_rn(deg0, C0), av);
                nxt[n0] = w;
                part += w * w;
            }
            if (v1) {
                float av = 0.0f;
                for (int j = 0; j < m1; j++) av = __fadd_rn(av, C0);
                float w = __fsub_rn(__fmul_rn(deg1, C0), av);
                nxt[n1] = w;
                part += w * w;
            }
        } else {
            // stage full iterate from L2 (written by all CTAs last iter)
            const float4* c4 = reinterpret_cast<const float4*>(cur);
            float4* s4 = reinterpret_cast<float4*>(sm);
            for (int i = tid; i < NN / 4; i += 1024)
                s4[i] = __ldcg(c4 + i);
            __syncthreads();

            float inv = 1.0f / sqrtf(__ldcg(&g_S[k - 1]));
            {
                float acc = deg0 * sm[n0];
                if (fastE) {
#pragma unroll 4
                    for (int j = 0; j < m0; j++) acc -= sm[se[l00 + j]];
                } else {
                    for (int j = 0; j < m0; j++) acc -= sm[g_col[ebase + l00 + j]];
                }
                acc *= inv;
                nxt[n0] = acc;
                part += acc * acc;
            }
            if (v1) {
                float acc = deg1 * sm[n1];
                if (fastE) {
#pragma unroll 4
                    for (int j = 0; j < m1; j++) acc -= sm[se[l01 + j]];
                } else {
                    for (int j = 0; j < m1; j++) acc -= sm[g_col[ebase + l01 + j]];
                }
                acc *= inv;
                nxt[n1] = acc;
                part += acc * acc;
            }
        }
        red[tid] = part; __syncthreads();
        for (int s = 512; s > 0; s >>= 1) {
            if (tid < s) red[tid] += red[tid + s];
            __syncthreads();
        }
        if (tid == 0) atomicAdd(&g_S[k], red[0]);
        __threadfence();
        asm volatile("barrier.cluster.arrive.aligned;" ::: "memory");
        asm volatile("barrier.cluster.wait.aligned;" ::: "memory");
        float* tmp = cur; cur = nxt; nxt = tmp;
    }
    float lm = sqrtf(__ldcg(&g_S[ITERS]));
    if (rank == 0 && tid == 0) g_lmax = lm;
    for (int i = (int)rank * 1024 + tid; i < NN; i += CSZ * 1024)
        g_diag[i] = 2.0f * (float)g_indeg[i] / lm - 1.0f;
}

// ---------------- permute X(B,N,F,T) -> Tx0 = (F,B,N,T) flat -------------
// The reference's reshape makes graph row n2 = flat[(n2*512):(n2*512+512)]
// of the (F,B,N,T) array, so this simple transpose IS the required layout
// (inner row layout: [f2(16)][tb(32)]).
__global__ void k_permute(const float* __restrict__ X) {
    int i = blockIdx.x * blockDim.x + threadIdx.x;   // [0, 640000)
    if (i >= NN * BB * FIN) return;
    int f = i / (BB * NN);
    int r = i - f * (BB * NN);
    int b = r / NN;
    int n = r - b * NN;
    const float4* src = reinterpret_cast<const float4*>(X + ((size_t)((b * NN + n) * FIN + f)) * TT);
    float4* dst = reinterpret_cast<float4*>(g_Tx0 + (size_t)i * TT);
    dst[0] = src[0];
    dst[1] = src[1];
}

// ---------------- lhat1: Tx1 = diag*Tx0 - off * A^T Tx0 -----------------
__global__ void k_lhat1() {
    int n = blockIdx.x;
    int t = threadIdx.x;   // 0..127, float4 chunk of the 512-float row
    const float4* x0 = reinterpret_cast<const float4*>(g_Tx0);
    float4 acc = make_float4(0.f, 0.f, 0.f, 0.f);
    int e0 = g_rowptr[n], e1 = g_rowptr[n + 1];
    for (int j = e0; j < e1; j++) {
        int s = g_col[j];
        float4 v = x0[s * 128 + t];
        acc.x += v.x; acc.y += v.y; acc.z += v.z; acc.w += v.w;
    }
    float off = 2.0f / g_lmax;
    float dg  = g_diag[n];
    float4 xx = x0[n * 128 + t];
    float4 o;
    o.x = dg * xx.x - off * acc.x;
    o.y = dg * xx.y - off * acc.y;
    o.z = dg * xx.z - off * acc.z;
    o.w = dg * xx.w - off * acc.w;
    reinterpret_cast<float4*>(g_Tx1)[n * 128 + t] = o;
}

// ------- lhat2 (Tx2 = 2*lhat(Tx1)-Tx0) fused with Cheb GEMM + ReLU ------
// Rows f-major: element (f2, tb) at local index f2*32 + tb.
__global__ void k_lhat2cheb(const float* __restrict__ chebW, const float* __restrict__ chebB) {
    __shared__ __align__(16) float sT[1536];   // Tx0,Tx1,Tx2 rows of this node
    __shared__ float sW[1536];                 // cheb_W (3,16,32)
    __shared__ float sB[CCH];
    int n = blockIdx.x;
    int t = threadIdx.x;   // 128 threads
    for (int i = t; i < 1536; i += 128) sW[i] = chebW[i];
    if (t < CCH) sB[t] = chebB[t];

    const float4* x0 = reinterpret_cast<const float4*>(g_Tx0);
    const float4* x1 = reinterpret_cast<const float4*>(g_Tx1);
    float4 acc = make_float4(0.f, 0.f, 0.f, 0.f);
    int e0 = g_rowptr[n], e1 = g_rowptr[n + 1];
    for (int j = e0; j < e1; j++) {
        int s = g_col[j];
        float4 v = x1[s * 128 + t];
        acc.x += v.x; acc.y += v.y; acc.z += v.z; acc.w += v.w;
    }
    float off = 2.0f / g_lmax;
    float dg  = g_diag[n];
    float4 a1 = x1[n * 128 + t];
    float4 a0 = x0[n * 128 + t];
    float4 t2;
    t2.x = 2.f * (dg * a1.x - off * acc.x) - a0.x;
    t2.y = 2.f * (dg * a1.y - off * acc.y) - a0.y;
    t2.z = 2.f * (dg * a1.z - off * acc.z) - a0.z;
    t2.w = 2.f * (dg * a1.w - off * acc.w) - a0.w;
    reinterpret_cast<float4*>(sT)[t]       = a0;   // Tx0 row (f-major)
    reinterpret_cast<float4*>(sT)[128 + t] = a1;   // Tx1 row
    reinterpret_cast<float4*>(sT)[256 + t] = t2;   // Tx2 row
    __syncthreads();

    // out[tb][c] = relu(b_c + sum_k sum_f Txk[f][tb]*W[k][f][c])
    int tb = t >> 2;
    int c0 = (t & 3) << 3;   // 8 channels per thread
    float y[8];
#pragma unroll
    for (int i = 0; i < 8; i++) y[i] = 0.f;
#pragma unroll
    for (int k = 0; k < 3; k++) {
        const float* xr = sT + k * 512 + tb;       // element f at xr[f*32]
        const float* wk = sW + k * 512;
#pragma unroll
        for (int f = 0; f < FIN; f++) {
            float xv = xr[f * 32];
            const float* wr = wk + f * 32 + c0;
#pragma unroll
            for (int i = 0; i < 8; i++) y[i] += xv * wr[i];
        }
    }
    float* outp = g_cheb + n * 1024 + tb * 32 + c0;
#pragma unroll
    for (int i = 0; i < 8; i++) outp[i] = fmaxf(y[i] + sB[c0 + i], 0.f);
}

// ------- final: time conv + residual + ReLU + LayerNorm + write ---------
// per (b,n) unit: Y(64x8) = A(64x112) * Z(112x8) + bias ; relu ; LN over 64
// GEMM uses packed fma.rn.f32x2 (identical rounding to scalar FFMA chain).
__global__ void k_final(const float* __restrict__ X,
                        const float* __restrict__ timeW, const float* __restrict__ timeB,
                        const float* __restrict__ resW,  const float* __restrict__ resB,
                        const float* __restrict__ gamma, const float* __restrict__ beta,
                        float* __restrict__ out) {
    __shared__ float As[112 * 64];                   // transposed: As[kk*64+co]
    __shared__ __align__(16) float Zs[4][896];       // per-group Z (112x8)
    __shared__ float sBias[64], sG[64], sBt[64];
    __shared__ float redS[4][2][8], redQ[4][2][8];
    int tid = threadIdx.x;

    for (int i = tid; i < 7168; i += 256) {
        int kk = i >> 6, co = i & 63;
        float w;
        if (kk < 96) { int ci = kk / 3, dt = kk - ci * 3; w = timeW[co * 96 + ci * 3 + dt]; }
        else         { w = resW[co * 16 + (kk - 96)]; }
        As[i] = w;
    }
    if (tid < 64) { sBias[tid] = timeB[tid] + resB[tid]; sG[tid] = gamma[tid]; sBt[tid] = beta[tid]; }
    __syncthreads();

    int g = tid >> 6, co = tid & 63;
    int lane = tid & 31, wsub = (tid >> 5) & 1;

    for (int round = 0; round < 8; round++) {
        int unit = blockIdx.x * 32 + round * 4 + g;   // 0..39999
        int b = unit / NN, n = unit - b * NN;

        // build Z: kk<96 -> time-conv patch (ci,dt), kk>=96 -> residual X
        const float* cbase = g_cheb + n * 1024 + b * 256;       // [tau*32+ci]
        const float* xbase = X + (size_t)(b * NN + n) * 128;    // [f*8+t]
        float* Z = Zs[g];
        for (int i = co; i < 896; i += 64) {
            int kk = i >> 3, t = i & 7;
            float v;
            if (kk < 96) {
                int ci = kk / 3, dt = kk - ci * 3;
                int tau = t + dt - 1;
                v = (tau >= 0 && tau < TT) ? cbase[tau * 32 + ci] : 0.f;
            } else {
                v = xbase[(kk - 96) * 8 + t];
            }
            Z[i] = v;
        }
        __syncthreads();

        float bco = sBias[co];
        unsigned long long y01 = pk2(bco, bco);
        unsigned long long y23 = pk2(bco, bco);
        unsigned long long y45 = pk2(bco, bco);
        unsigned long long y67 = pk2(bco, bco);
        const float4* Z4 = reinterpret_cast<const float4*>(Z);
        const float*  Ap = As + co;
#pragma unroll 4
        for (int kk = 0; kk < 112; kk++) {
            float a = Ap[kk * 64];
            unsigned long long aa = pk2(a, a);
            float4 z0 = Z4[kk * 2];
            float4 z1 = Z4[kk * 2 + 1];
            fma2(y01, aa, pk2(z0.x, z0.y));
            fma2(y23, aa, pk2(z0.z, z0.w));
            fma2(y45, aa, pk2(z1.x, z1.y));
            fma2(y67, aa, pk2(z1.z, z1.w));
        }
        float y[8];
        { float2 p = upk2(y01); y[0] = p.x; y[1] = p.y; }
        { float2 p = upk2(y23); y[2] = p.x; y[3] = p.y; }
        { float2 p = upk2(y45); y[4] = p.x; y[5] = p.y; }
        { float2 p = upk2(y67); y[6] = p.x; y[7] = p.y; }
#pragma unroll
        for (int t = 0; t < 8; t++) y[t] = fmaxf(y[t], 0.f);

        // LayerNorm over 64 channels — two-pass (matches jnp.var semantics)
        float s[8];
#pragma unroll
        for (int t = 0; t < 8; t++) s[t] = y[t];
#pragma unroll
        for (int off = 16; off > 0; off >>= 1) {
#pragma unroll
            for (int t = 0; t < 8; t++) s[t] += __shfl_xor_sync(0xffffffffu, s[t], off);
        }
        if (lane == 0) {
#pragma unroll
            for (int t = 0; t < 8; t++) redS[g][wsub][t] = s[t];
        }
        __syncthreads();

        float mu[8], q[8];
#pragma unroll
        for (int t = 0; t < 8; t++) {
            mu[t] = (redS[g][0][t] + redS[g][1][t]) * (1.f / 64.f);
            float d = y[t] - mu[t];
            q[t] = d * d;
        }
#pragma unroll
        for (int off = 16; off > 0; off >>= 1) {
#pragma unroll
            for (int t = 0; t < 8; t++) q[t] += __shfl_xor_sync(0xffffffffu, q[t], off);
        }
        if (lane == 0) {
#pragma unroll
            for (int t = 0; t < 8; t++) redQ[g][wsub][t] = q[t];
        }
        __syncthreads();

        float ov[8];
#pragma unroll
        for (int t = 0; t < 8; t++) {
            float var = (redQ[g][0][t] + redQ[g][1][t]) * (1.f / 64.f);
            float inv = rsqrtf(var + 1e-5f);
            ov[t] = (y[t] - mu[t]) * inv * sG[co] + sBt[co];
        }
        float4* op = reinterpret_cast<float4*>(out + ((size_t)unit * 64 + co) * 8);
        op[0] = make_float4(ov[0], ov[1], ov[2], ov[3]);
        op[1] = make_float4(ov[4], ov[5], ov[6], ov[7]);
    }
}

// ---------------- launch ----------------
extern "C" void kernel_launch(void* const* d_in, const int* in_sizes, int n_in,
                              void* d_out, int out_size) {
    const float* X     = (const float*)d_in[0];
    const int*   ei    = (const int*)  d_in[1];
    const float* chebW = (const float*)d_in[2];
    const float* chebB = (const float*)d_in[3];
    const float* timeW = (const float*)d_in[4];
    const float* timeB = (const float*)d_in[5];
    const float* resW  = (const float*)d_in[6];
    const float* resB  = (const float*)d_in[7];
    const float* gam   = (const float*)d_in[8];
    const float* bet   = (const float*)d_in[9];
    float* out = (float*)d_out;

    int E = in_sizes[1] / 2;
    const int* src = ei;
    const int* dst = ei + E;
    int EB = (E + 255) / 256;

    const int PSMEM = (NN + ECAP) * (int)sizeof(float);   // 136000 B
    static int smem_set = 0;
    if (!smem_set) {
        cudaFuncSetAttribute(k_power, cudaFuncAttributeMaxDynamicSharedMemorySize, PSMEM);
        smem_set = 1;
    }

    k_zero<<<(NN + 255) / 256, 256>>>();
    k_hist<<<EB, 256>>>(dst, E);
    k_scan<<<1, 1024>>>();
    k_fill<<<EB, 256>>>(src, dst, E);
    k_power<<<CSZ, 1024, PSMEM>>>();
    k_permute<<<(NN * BB * FIN + 255) / 256, 256>>>(X);
    k_lhat1<<<NN, 128>>>();
    k_lhat2cheb<<<NN, 128>>>(chebW, chebB);
    k_final<<<1250, 256>>>(X, timeW, timeB, resW, resB, gam, bet, out);
}